// round 12
// baseline (speedup 1.0000x reference)
#include <cuda_runtime.h>
#include <math.h>
#include <cstdint>

#define HH 2048
#define WW 2048
#define NPB (HH*WW)            // 4,194,304 elems per batch
#define NF4 (NPB/4)            // 1,048,576 float4 per batch
#define BATCH 8
#define BPB 128                // blocks per batch
#define T1 256                 // threads per block
#define NBLK (BPB*BATCH)       // 1024 total blocks
#define F4PB (NF4/BPB)         // 8192 float4 per block (128 KB contiguous)
#define ITERS (F4PB/T1)        // 32 iterations, 4 KB contiguous per block-iter
#define WIN 5

// Scratch (device globals — no allocation in kernel_launch)
__device__ float g_pmax[NBLK];
__device__ int   g_pidx[NBLK];
__device__ float g_psum[NBLK];
__device__ float g_psq [NBLK];
__device__ int   g_pcnt[NBLK];
__device__ int   g_counter;      // zero-init; reset by the last block each run

__global__ void __launch_bounds__(T1, 8) psr_fused(const float* __restrict__ resp,
                                                   float* __restrict__ out) {
    const int b = blockIdx.y;
    // Contiguous ownership: block x owns float4s [x*F4PB, (x+1)*F4PB)
    const int base = blockIdx.x * F4PB + threadIdx.x;
    const float4* __restrict__ p = (const float4*)(resp + (size_t)b * NPB);

    float mx = -INFINITY;
    int   midx = 0;
    float s = 0.f, sq = 0.f; int c = 0;

    #pragma unroll 4
    for (int k = 0; k < ITERS; k++) {
        const int i = base + k * T1;                     // block sweeps 128KB sequentially
        const float4 v = p[(size_t)i];
        float m;
        m = fmaxf(v.x, 0.f); s += m; sq = fmaf(m, m, sq); c += (v.x > 0.f);
        m = fmaxf(v.y, 0.f); s += m; sq = fmaf(m, m, sq); c += (v.y > 0.f);
        m = fmaxf(v.z, 0.f); s += m; sq = fmaf(m, m, sq); c += (v.z > 0.f);
        m = fmaxf(v.w, 0.f); s += m; sq = fmaf(m, m, sq); c += (v.w > 0.f);
        const float vm = fmaxf(fmaxf(v.x, v.y), fmaxf(v.z, v.w));
        if (vm > mx) {                                   // rare
            mx = vm;
            int comp = 3;
            if (v.z == vm) comp = 2;
            if (v.y == vm) comp = 1;
            if (v.x == vm) comp = 0;
            midx = i * 4 + comp;
        }
    }

    // ---- intra-warp reduce ----
    const unsigned FULL = 0xFFFFFFFFu;
    #pragma unroll
    for (int off = 16; off > 0; off >>= 1) {
        float om = __shfl_down_sync(FULL, mx, off);
        int   oi = __shfl_down_sync(FULL, midx, off);
        if (om > mx || (om == mx && oi < midx)) { mx = om; midx = oi; }
        s  += __shfl_down_sync(FULL, s,  off);
        sq += __shfl_down_sync(FULL, sq, off);
        c  += __shfl_down_sync(FULL, c,  off);
    }

    // ---- cross-warp reduce via smem (8 warps) ----
    __shared__ float wmax[8]; __shared__ int widx[8];
    __shared__ float wsum[8]; __shared__ float wsq[8]; __shared__ int wcnt[8];
    const int lane = threadIdx.x & 31;
    const int wid  = threadIdx.x >> 5;
    if (lane == 0) { wmax[wid] = mx; widx[wid] = midx; wsum[wid] = s; wsq[wid] = sq; wcnt[wid] = c; }
    __syncthreads();

    if (wid == 0) {
        mx   = (lane < 8) ? wmax[lane] : -INFINITY;
        midx = (lane < 8) ? widx[lane] : 0x7FFFFFFF;
        s    = (lane < 8) ? wsum[lane] : 0.f;
        sq   = (lane < 8) ? wsq[lane]  : 0.f;
        c    = (lane < 8) ? wcnt[lane] : 0;
        #pragma unroll
        for (int off = 4; off > 0; off >>= 1) {
            float om = __shfl_down_sync(FULL, mx, off);
            int   oi = __shfl_down_sync(FULL, midx, off);
            if (om > mx || (om == mx && oi < midx)) { mx = om; midx = oi; }
            s  += __shfl_down_sync(FULL, s,  off);
            sq += __shfl_down_sync(FULL, sq, off);
            c  += __shfl_down_sync(FULL, c,  off);
        }
        if (lane == 0) {
            const int o = b * BPB + blockIdx.x;
            g_pmax[o] = mx; g_pidx[o] = midx; g_psum[o] = s; g_psq[o] = sq; g_pcnt[o] = c;
        }
    }

    // ---- last-block-done ----
    __shared__ int is_last;
    __threadfence();
    __syncthreads();
    if (threadIdx.x == 0) {
        int prev = atomicAdd(&g_counter, 1);
        is_last = (prev == NBLK - 1);
    }
    __syncthreads();
    if (!is_last) return;

    // ================= finalize (parallel, float tree reductions) =============
    __shared__ float fmx [NBLK];
    __shared__ int   fidx[NBLK];
    __shared__ float fsum[NBLK];
    __shared__ float fsq [NBLK];
    __shared__ int   fcnt[NBLK];
    __shared__ float spsr[8];

    #pragma unroll
    for (int j = threadIdx.x; j < NBLK; j += T1) {
        fmx [j] = g_pmax[j];
        fidx[j] = g_pidx[j];
        fsum[j] = g_psum[j];
        fsq [j] = g_psq[j];
        fcnt[j] = g_pcnt[j];
    }
    __syncthreads();

    {
        const int w = threadIdx.x >> 5;     // batch
        const int l = threadIdx.x & 31;

        float bmx = -INFINITY; int bmi = 0x7FFFFFFF;
        float bs = 0.f, bq = 0.f; int bc = 0;
        #pragma unroll
        for (int t = 0; t < 4; t++) {
            const int o = w * BPB + l + t * 32;
            const float pm = fmx[o]; const int pi = fidx[o];
            if (pm > bmx || (pm == bmx && pi < bmi)) { bmx = pm; bmi = pi; }
            bs += fsum[o]; bq += fsq[o]; bc += fcnt[o];
        }
        #pragma unroll
        for (int off = 16; off > 0; off >>= 1) {
            float om = __shfl_down_sync(FULL, bmx, off);
            int   oi = __shfl_down_sync(FULL, bmi, off);
            if (om > bmx || (om == bmx && oi < bmi)) { bmx = om; bmi = oi; }
            bs += __shfl_down_sync(FULL, bs, off);
            bq += __shfl_down_sync(FULL, bq, off);
            bc += __shfl_down_sync(FULL, bc, off);
        }
        bmi = __shfl_sync(FULL, bmi, 0);
        const int cy = bmi / WW, cx = bmi % WW;

        // 11x11 window correction: 121 elems over 32 lanes, 4 indep loads/lane.
        float ws = 0.f, wq = 0.f; int wc = 0;
        #pragma unroll
        for (int t = 0; t < 4; t++) {
            const int it = l + t * 32;
            if (it < (2*WIN+1)*(2*WIN+1)) {
                const int y = cy + it / (2*WIN+1) - WIN;
                const int x = cx + it % (2*WIN+1) - WIN;
                if (y >= 0 && y < HH && x >= 0 && x < WW) {
                    const float v = resp[(size_t)w * NPB + (size_t)y * WW + x];
                    if (v > 0.f) { ws += v; wq = fmaf(v, v, wq); wc++; }
                }
            }
        }
        #pragma unroll
        for (int off = 16; off > 0; off >>= 1) {
            ws += __shfl_down_sync(FULL, ws, off);
            wq += __shfl_down_sync(FULL, wq, off);
            wc += __shfl_down_sync(FULL, wc, off);
        }
        if (l == 0) {
            const double n    = (double)(bc - wc);
            const double sum  = (double)bs - (double)ws;
            const double sqs  = (double)bq - (double)wq;
            const double mean = sum / n;
            const double var  = (sqs - n * mean * mean) / (n - 1.0);
            const float  stdv = (float)sqrt(var);
            spsr[w] = (float)((double)bmx - mean) / (stdv + 1e-5f);
        }
    }
    __syncthreads();
    if (threadIdx.x == 0) {
        float acc = 0.f;
        #pragma unroll
        for (int i = 0; i < BATCH; i++) acc += spsr[i];
        out[0] = acc / (float)BATCH;
        g_counter = 0;   // only block left; safe reset for next graph replay
    }
}

extern "C" void kernel_launch(void* const* d_in, const int* in_sizes, int n_in,
                              void* d_out, int out_size) {
    const float* resp = (const float*)d_in[0];
    float* out = (float*)d_out;
    dim3 grid(BPB, BATCH);
    psr_fused<<<grid, T1>>>(resp, out);
}